// round 5
// baseline (speedup 1.0000x reference)
#include <cuda_runtime.h>
#include <cstdint>

// ---------------- config ----------------
#define THREADS   256            // 8 fully independent warps
#define WARPS     8
#define QPW       2              // queries per warp per iteration (8KB chunk)
#define CHUNK_BYTES (QPW * 4096) // 8192
#define QFLOATS   1024           // 128 * 8 floats per query
#define QBYTES    4096
#define STAGES    3              // per-warp ring depth
#define RING_BYTES (STAGES * CHUNK_BYTES)           // 24576 per warp
#define SMEM_TOTAL (1024 + WARPS * RING_BYTES)      // 197632

using u32 = unsigned int;
using u64 = unsigned long long;

// ---------------- small PTX helpers ----------------
__device__ __forceinline__ u32 s2u(const void* p) {
    u32 a;
    asm("{ .reg .u64 t; cvta.to.shared.u64 t, %1; cvt.u32.u64 %0, t; }"
        : "=r"(a) : "l"(p));
    return a;
}
__device__ __forceinline__ u64 pack2(float x, float y) {
    u64 r; asm("mov.b64 %0, {%1, %2};" : "=l"(r) : "f"(x), "f"(y)); return r;
}
__device__ __forceinline__ float2 unpack2(u64 v) {
    float2 f; asm("mov.b64 {%0, %1}, %2;" : "=f"(f.x), "=f"(f.y) : "l"(v)); return f;
}
__device__ __forceinline__ u64 fma2(u64 a, u64 b, u64 c) {
    u64 d; asm("fma.rn.f32x2 %0, %1, %2, %3;" : "=l"(d) : "l"(a), "l"(b), "l"(c));
    return d;
}
__device__ __forceinline__ void mbar_init(u32 m, u32 cnt) {
    asm volatile("mbarrier.init.shared.b64 [%0], %1;" :: "r"(m), "r"(cnt) : "memory");
}
__device__ __forceinline__ void mbar_expect(u32 m, u32 bytes) {
    asm volatile("mbarrier.arrive.expect_tx.shared.b64 _, [%0], %1;"
                 :: "r"(m), "r"(bytes) : "memory");
}
__device__ __forceinline__ void mbar_wait(u32 m, u32 parity) {
    asm volatile(
        "{\n\t"
        ".reg .pred P;\n\t"
        "W1_%=:\n\t"
        "mbarrier.try_wait.parity.acquire.cta.shared::cta.b64 P, [%0], %1, 0x989680;\n\t"
        "@P bra.uni W2_%=;\n\t"
        "bra.uni W1_%=;\n\t"
        "W2_%=:\n\t"
        "}"
        :: "r"(m), "r"(parity) : "memory");
}
__device__ __forceinline__ void bulk_g2s(u32 dst, const void* src, u32 bytes, u32 mbar) {
    asm volatile(
        "cp.async.bulk.shared::cluster.global.mbarrier::complete_tx::bytes [%0], [%1], %2, [%3];"
        :: "r"(dst), "l"(src), "r"(bytes), "r"(mbar) : "memory");
}
__device__ __forceinline__ bool elect1() {
    u32 p;
    asm volatile("{ .reg .pred P; elect.sync _|P, 0xFFFFFFFF; selp.b32 %0,1,0,P; }"
                 : "=r"(p));
    return p != 0;
}

// ---------------- alpha computation (factorized Gaussian softmax) ----------------
struct Alpha { u64 ap[4]; u64 alo, ahi; };

__device__ __forceinline__ Alpha alpha_from_cell(float2 c, int lane) {
    const float LOGS0     = -4.8520303f;   // log(2/256)
    const float TAU_SCALE =  2.0580988f;   // 7 / log(30)
    const float DK[8] = {1.0f, 0.45783335f, 0.09596708f, 0.02011565f,
                         0.00421647f, 0.00088382f, 1.852587e-4f, 3.883240e-5f};
    float pr  = fmaxf(c.x * c.y, 1e-20f);
    float tau = (LOGS0 - 0.5f * __logf(pr)) * TAU_SCALE;
    tau = fminf(fmaxf(tau, 0.0f), 7.0f);
    float r = __expf(tau * 1.5625f);
    float pk[8];
    pk[0] = 1.0f;
    float ssum = 1.0f;
    #pragma unroll
    for (int k = 1; k < 8; k++) { pk[k] = pk[k - 1] * (r * DK[k]); ssum += pk[k]; }
    float inv = __fdividef(1.0f, ssum);
    float a[8];
    #pragma unroll
    for (int k = 0; k < 8; k++) a[k] = pk[k] * inv;
    Alpha A;
    #pragma unroll
    for (int kp = 0; kp < 4; kp++) A.ap[kp] = pack2(a[2 * kp], a[2 * kp + 1]);
    A.alo = (lane & 1) ? A.ap[2] : A.ap[0];
    A.ahi = (lane & 1) ? A.ap[3] : A.ap[1];
    return A;
}

// ---------------- kernel ----------------
// h:    [BQ, 128, 8] f32 (4KB per query, contiguous)
// cell: [BQ, 2] f32
// W:    [8, 3, 128] f32  (to_rgb_weight[k][o][c])
// B:    [8, 3] f32
// out:  [BQ, 3] f32
//
// Per-warp 3-stage x 8KB smem ring, warp self-issues TMA refills, no cross-
// warp sync after init. Lane l covers float4s at byte offsets {j*512+l*16}:
//   c = 16*j + (l>>1),  k in [4*(l&1), 4*(l&1)+4)
// alpha is computed one iteration ahead so the pre-consume critical path is
// just mbar_wait -> FMA; refill TMA is issued before the shuffle epilogue.
__global__ void __launch_bounds__(THREADS, 1)
gsr_kernel(const float* __restrict__ h, const float* __restrict__ cell,
           const float* __restrict__ W, const float* __restrict__ B,
           float* __restrict__ out, int BQ)
{
    extern __shared__ char smem[];
    const u32 smem_base = s2u(smem);

    const int tid  = threadIdx.x;
    const int warp = tid >> 5;
    const int lane = tid & 31;

    const u32 mybar = smem_base + (u32)warp * (8u * STAGES);
    char* const myring = smem + 1024 + (size_t)warp * RING_BYTES;
    const u32 myring_u = smem_base + 1024u + (u32)warp * RING_BYTES;

    if (lane == 0) {
        #pragma unroll
        for (int s = 0; s < STAGES; s++) mbar_init(mybar + 8u * s, 1);
    }
    __syncthreads();   // only CTA sync: barrier-init visibility

    // ---- per-lane register weights ----
    const int kb = (lane & 1) * 4;
    const int ch = lane >> 1;
    u64 wreg[2][3][8];
    #pragma unroll
    for (int kp = 0; kp < 2; kp++)
        #pragma unroll
        for (int o = 0; o < 3; o++)
            #pragma unroll
            for (int j = 0; j < 8; j++) {
                const int k0 = kb + 2 * kp;
                const int c  = 16 * j + ch;
                wreg[kp][o][j] = pack2(W[(k0 * 3 + o) * 128 + c],
                                       W[((k0 + 1) * 3 + o) * 128 + c]);
            }
    const int o_l = lane < 3 ? lane : 0;
    u64 bpl[4];
    #pragma unroll
    for (int kp = 0; kp < 4; kp++)
        bpl[kp] = pack2(B[(2 * kp) * 3 + o_l], B[(2 * kp + 1) * 3 + o_l]);

    const int NP = (BQ + QPW - 1) / QPW;
    const int TW = gridDim.x * WARPS;
    const int pb = blockIdx.x * WARPS + warp;

    // ---- prologue: fill my 3 stages ----
    if (elect1()) {
        #pragma unroll
        for (int p = 0; p < STAGES; ++p) {
            int pair = pb + p * TW;
            if (pair < NP) {
                int cnt = min(QPW, BQ - pair * QPW);
                u32 bytes = (u32)cnt * QBYTES;
                mbar_expect(mybar + 8u * p, bytes);
                bulk_g2s(myring_u + (u32)p * CHUNK_BYTES,
                         h + (size_t)pair * QPW * QFLOATS, bytes, mybar + 8u * p);
            }
        }
    }

    const float2* cell2 = (const float2*)cell;

    // ---- prologue: alpha for first pair, prefetch cell for second ----
    Alpha A[QPW];
    float2 cr[QPW];
    {
        int qb = pb * QPW;
        float2 c0[QPW];
        #pragma unroll
        for (int i = 0; i < QPW; i++)
            c0[i] = (qb + i < BQ) ? __ldg(cell2 + qb + i) : make_float2(1.f, 1.f);
        #pragma unroll
        for (int i = 0; i < QPW; i++) A[i] = alpha_from_cell(c0[i], lane);
        int qn = (pb + TW) * QPW;
        #pragma unroll
        for (int i = 0; i < QPW; i++)
            cr[i] = (qn + i < BQ && pb + TW < NP) ? __ldg(cell2 + qn + i)
                                                  : make_float2(1.f, 1.f);
    }

    int it = 0;
    for (int pair = pb; pair < NP; pair += TW, ++it) {
        const int s   = it % STAGES;
        const u32 par = (u32)((it / STAGES) & 1);
        const int qb  = pair * QPW;

        // ---- consume my staged chunk (alpha already in regs) ----
        mbar_wait(mybar + 8u * s, par);

        const char* sb = myring + (size_t)s * CHUNK_BYTES;
        float y[QPW][3];
        #pragma unroll
        for (int i = 0; i < QPW; i++) {
            const char* qs = sb + (size_t)i * QBYTES + (size_t)lane * 16;
            u64 acc0[3] = {0ULL, 0ULL, 0ULL};
            u64 acc1[3] = {0ULL, 0ULL, 0ULL};
            #pragma unroll
            for (int j = 0; j < 8; j++) {
                ulonglong2 h2 = *(const ulonglong2*)(qs + j * 512);
                #pragma unroll
                for (int o = 0; o < 3; o++) {
                    acc0[o] = fma2(h2.x, wreg[0][o][j], acc0[o]);
                    acc1[o] = fma2(h2.y, wreg[1][o][j], acc1[o]);
                }
            }
            #pragma unroll
            for (int o = 0; o < 3; o++) {
                u64 t2 = fma2(A[i].alo, acc0[o], fma2(A[i].ahi, acc1[o], 0ULL));
                float2 f = unpack2(t2);
                y[i][o] = f.x + f.y;
            }
        }

        // ---- refill stage s immediately (smem reads consumed by dataflow) ----
        {
            int pn = pair + STAGES * TW;
            if (pn < NP && elect1()) {
                int cnt = min(QPW, BQ - pn * QPW);
                u32 bytes = (u32)cnt * QBYTES;
                mbar_expect(mybar + 8u * s, bytes);
                bulk_g2s(myring_u + (u32)s * CHUNK_BYTES,
                         h + (size_t)pn * QPW * QFLOATS, bytes, mybar + 8u * s);
            }
        }

        // ---- compute NEXT pair's alpha (MUFU chain overlaps epilogue below) ----
        Alpha An[QPW];
        #pragma unroll
        for (int i = 0; i < QPW; i++) An[i] = alpha_from_cell(cr[i], lane);

        // ---- prefetch cell two pairs ahead ----
        {
            int pn = pair + 2 * TW;
            if (pn < NP) {
                int qn = pn * QPW;
                #pragma unroll
                for (int i = 0; i < QPW; i++)
                    cr[i] = (qn + i < BQ) ? __ldg(cell2 + qn + i) : make_float2(1.f, 1.f);
            }
        }

        // ---- reduce across lanes: 6 interleaved butterfly chains ----
        #pragma unroll
        for (int d = 16; d > 0; d >>= 1) {
            #pragma unroll
            for (int i = 0; i < QPW; i++)
                #pragma unroll
                for (int o = 0; o < 3; o++)
                    y[i][o] += __shfl_xor_sync(0xffffffffu, y[i][o], d);
        }

        // ---- store (+ bias dot, lane==o) ----
        #pragma unroll
        for (int i = 0; i < QPW; i++) {
            int q = qb + i;
            if (q < BQ && lane < 3) {
                u64 bd = 0ULL;
                #pragma unroll
                for (int kp = 0; kp < 4; kp++) bd = fma2(A[i].ap[kp], bpl[kp], bd);
                float2 f = unpack2(bd);
                float val = ((lane == 0) ? y[i][0] : (lane == 1) ? y[i][1] : y[i][2])
                            + f.x + f.y;
                out[3 * (size_t)q + lane] = val;
            }
        }

        // ---- rotate alpha pipeline ----
        #pragma unroll
        for (int i = 0; i < QPW; i++) A[i] = An[i];
    }
}

// ---------------- launch ----------------
extern "C" void kernel_launch(void* const* d_in, const int* in_sizes, int n_in,
                              void* d_out, int out_size)
{
    (void)n_in; (void)out_size;
    const float* h    = (const float*)d_in[0];
    const float* cell = (const float*)d_in[1];
    const float* W    = (const float*)d_in[2];
    const float* B    = (const float*)d_in[3];
    float* out = (float*)d_out;

    const int BQ = in_sizes[1] / 2;

    int dev = 0;
    cudaGetDevice(&dev);
    int sm = 0;
    cudaDeviceGetAttribute(&sm, cudaDevAttrMultiProcessorCount, dev);
    if (sm <= 0) sm = 148;

    cudaFuncSetAttribute(gsr_kernel, cudaFuncAttributeMaxDynamicSharedMemorySize, SMEM_TOTAL);
    gsr_kernel<<<sm, THREADS, SMEM_TOTAL>>>(h, cell, W, B, out, BQ);
}

// round 6
// speedup vs baseline: 1.1777x; 1.1777x over previous
#include <cuda_runtime.h>
#include <cstdint>

// ---------------- config ----------------
#define THREADS   128            // 4 independent warps per CTA
#define WARPS     4
#define CTAS_PER_SM 2            // -> 16 warps / SM, 4 per SMSP
#define QPW       2              // queries per warp per iteration (8KB chunk)
#define CHUNK_BYTES (QPW * 4096) // 8192
#define QFLOATS   1024           // 128 * 8 floats per query
#define QBYTES    4096
#define STAGES    3              // per-warp ring depth
#define RING_BYTES (STAGES * CHUNK_BYTES)           // 24576 per warp
#define SMEM_TOTAL (1024 + WARPS * RING_BYTES)      // 99328 per CTA (x2 fits 227KB)

using u32 = unsigned int;
using u64 = unsigned long long;

// ---------------- small PTX helpers ----------------
__device__ __forceinline__ u32 s2u(const void* p) {
    u32 a;
    asm("{ .reg .u64 t; cvta.to.shared.u64 t, %1; cvt.u32.u64 %0, t; }"
        : "=r"(a) : "l"(p));
    return a;
}
__device__ __forceinline__ u64 pack2(float x, float y) {
    u64 r; asm("mov.b64 %0, {%1, %2};" : "=l"(r) : "f"(x), "f"(y)); return r;
}
__device__ __forceinline__ float2 unpack2(u64 v) {
    float2 f; asm("mov.b64 {%0, %1}, %2;" : "=f"(f.x), "=f"(f.y) : "l"(v)); return f;
}
__device__ __forceinline__ u64 fma2(u64 a, u64 b, u64 c) {
    u64 d; asm("fma.rn.f32x2 %0, %1, %2, %3;" : "=l"(d) : "l"(a), "l"(b), "l"(c));
    return d;
}
__device__ __forceinline__ void mbar_init(u32 m, u32 cnt) {
    asm volatile("mbarrier.init.shared.b64 [%0], %1;" :: "r"(m), "r"(cnt) : "memory");
}
__device__ __forceinline__ void mbar_expect(u32 m, u32 bytes) {
    asm volatile("mbarrier.arrive.expect_tx.shared.b64 _, [%0], %1;"
                 :: "r"(m), "r"(bytes) : "memory");
}
__device__ __forceinline__ void mbar_wait(u32 m, u32 parity) {
    asm volatile(
        "{\n\t"
        ".reg .pred P;\n\t"
        "W1_%=:\n\t"
        "mbarrier.try_wait.parity.acquire.cta.shared::cta.b64 P, [%0], %1, 0x989680;\n\t"
        "@P bra.uni W2_%=;\n\t"
        "bra.uni W1_%=;\n\t"
        "W2_%=:\n\t"
        "}"
        :: "r"(m), "r"(parity) : "memory");
}
__device__ __forceinline__ void bulk_g2s(u32 dst, const void* src, u32 bytes, u32 mbar) {
    asm volatile(
        "cp.async.bulk.shared::cluster.global.mbarrier::complete_tx::bytes [%0], [%1], %2, [%3];"
        :: "r"(dst), "l"(src), "r"(bytes), "r"(mbar) : "memory");
}
__device__ __forceinline__ bool elect1() {
    u32 p;
    asm volatile("{ .reg .pred P; elect.sync _|P, 0xFFFFFFFF; selp.b32 %0,1,0,P; }"
                 : "=r"(p));
    return p != 0;
}

// ---------------- kernel ----------------
// h:    [BQ, 128, 8] f32 (4KB per query, contiguous)
// cell: [BQ, 2] f32
// W:    [8, 3, 128] f32  (to_rgb_weight[k][o][c])
// B:    [8, 3] f32
// out:  [BQ, 3] f32
//
// Warp-autonomous: each warp owns a private 3-stage x 8KB smem ring and
// self-issues its bulk-async refills; no cross-warp sync after init.
// 128-thread CTAs at 2 CTAs/SM -> 4 warps/SMSP so warp multiplexing hides
// each warp's serial chains (mbar wake, alpha MUFU, shuffle reduction).
// Lane l covers float4s at byte offsets {j*512 + l*16, j=0..7}:
//   c = 16*j + (l>>1),  k in [4*(l&1), 4*(l&1)+4)
__global__ void __launch_bounds__(THREADS, CTAS_PER_SM)
gsr_kernel(const float* __restrict__ h, const float* __restrict__ cell,
           const float* __restrict__ W, const float* __restrict__ B,
           float* __restrict__ out, int BQ)
{
    extern __shared__ char smem[];
    const u32 smem_base = s2u(smem);

    const int tid  = threadIdx.x;
    const int warp = tid >> 5;
    const int lane = tid & 31;

    const u32 mybar = smem_base + (u32)warp * (8u * STAGES);
    char* const myring = smem + 1024 + (size_t)warp * RING_BYTES;
    const u32 myring_u = smem_base + 1024u + (u32)warp * RING_BYTES;

    if (lane == 0) {
        #pragma unroll
        for (int s = 0; s < STAGES; s++) mbar_init(mybar + 8u * s, 1);
    }
    __syncthreads();   // only CTA sync: barrier-init visibility

    // ---- per-lane register weights ----
    const int kb = (lane & 1) * 4;
    const int ch = lane >> 1;
    u64 wreg[2][3][8];
    #pragma unroll
    for (int kp = 0; kp < 2; kp++)
        #pragma unroll
        for (int o = 0; o < 3; o++)
            #pragma unroll
            for (int j = 0; j < 8; j++) {
                const int k0 = kb + 2 * kp;
                const int c  = 16 * j + ch;
                wreg[kp][o][j] = pack2(W[(k0 * 3 + o) * 128 + c],
                                       W[((k0 + 1) * 3 + o) * 128 + c]);
            }
    const int o_l = lane < 3 ? lane : 0;
    u64 bpl[4];
    #pragma unroll
    for (int kp = 0; kp < 4; kp++)
        bpl[kp] = pack2(B[(2 * kp) * 3 + o_l], B[(2 * kp + 1) * 3 + o_l]);

    const int NP = (BQ + QPW - 1) / QPW;
    const int TW = gridDim.x * WARPS;
    const int pb = blockIdx.x * WARPS + warp;

    // ---- prologue: fill my 3 stages ----
    if (elect1()) {
        #pragma unroll
        for (int p = 0; p < STAGES; ++p) {
            int pair = pb + p * TW;
            if (pair < NP) {
                int cnt = min(QPW, BQ - pair * QPW);
                u32 bytes = (u32)cnt * QBYTES;
                mbar_expect(mybar + 8u * p, bytes);
                bulk_g2s(myring_u + (u32)p * CHUNK_BYTES,
                         h + (size_t)pair * QPW * QFLOATS, bytes, mybar + 8u * p);
            }
        }
    }

    // constants
    const float LOGS0     = -4.8520303f;   // log(2/256)
    const float TAU_SCALE =  2.0580988f;   // 7 / log(30)
    const float DK[8] = {1.0f, 0.45783335f, 0.09596708f, 0.02011565f,
                         0.00421647f, 0.00088382f, 1.852587e-4f, 3.883240e-5f};

    // ---- preload cell for first pair ----
    const float2* cell2 = (const float2*)cell;
    float2 cr[QPW];
    {
        int qb = pb * QPW;
        #pragma unroll
        for (int i = 0; i < QPW; i++)
            cr[i] = (qb + i < BQ) ? __ldg(cell2 + qb + i) : make_float2(1.f, 1.f);
    }

    int it = 0;
    for (int pair = pb; pair < NP; pair += TW, ++it) {
        const int s   = it % STAGES;
        const u32 par = (u32)((it / STAGES) & 1);
        const int qb  = pair * QPW;

        // ---- alpha from prefetched cell regs ----
        u64 ap[QPW][4], alo[QPW], ahi[QPW];
        #pragma unroll
        for (int i = 0; i < QPW; i++) {
            float pr  = fmaxf(cr[i].x * cr[i].y, 1e-20f);
            float tau = (LOGS0 - 0.5f * __logf(pr)) * TAU_SCALE;
            tau = fminf(fmaxf(tau, 0.0f), 7.0f);
            float r = __expf(tau * 1.5625f);
            float pk[8];
            pk[0] = 1.0f;
            float ssum = 1.0f;
            #pragma unroll
            for (int k = 1; k < 8; k++) {
                pk[k] = pk[k - 1] * (r * DK[k]);
                ssum += pk[k];
            }
            float inv = __fdividef(1.0f, ssum);
            float a[8];
            #pragma unroll
            for (int k = 0; k < 8; k++) a[k] = pk[k] * inv;
            #pragma unroll
            for (int kp = 0; kp < 4; kp++) ap[i][kp] = pack2(a[2 * kp], a[2 * kp + 1]);
            alo[i] = (lane & 1) ? ap[i][2] : ap[i][0];
            ahi[i] = (lane & 1) ? ap[i][3] : ap[i][1];
        }

        // ---- prefetch cell for NEXT pair ----
        {
            int pn = pair + TW;
            if (pn < NP) {
                int qn = pn * QPW;
                #pragma unroll
                for (int i = 0; i < QPW; i++)
                    cr[i] = (qn + i < BQ) ? __ldg(cell2 + qn + i) : make_float2(1.f, 1.f);
            }
        }

        // ---- consume my staged chunk ----
        mbar_wait(mybar + 8u * s, par);

        const char* sb = myring + (size_t)s * CHUNK_BYTES;
        float y[QPW][3];
        #pragma unroll
        for (int i = 0; i < QPW; i++) {
            const char* qs = sb + (size_t)i * QBYTES + (size_t)lane * 16;
            u64 acc0[3] = {0ULL, 0ULL, 0ULL};
            u64 acc1[3] = {0ULL, 0ULL, 0ULL};
            #pragma unroll
            for (int j = 0; j < 8; j++) {
                ulonglong2 h2 = *(const ulonglong2*)(qs + j * 512);
                #pragma unroll
                for (int o = 0; o < 3; o++) {
                    acc0[o] = fma2(h2.x, wreg[0][o][j], acc0[o]);
                    acc1[o] = fma2(h2.y, wreg[1][o][j], acc1[o]);
                }
            }
            #pragma unroll
            for (int o = 0; o < 3; o++) {
                u64 t2 = fma2(alo[i], acc0[o], fma2(ahi[i], acc1[o], 0ULL));
                float2 f = unpack2(t2);
                y[i][o] = f.x + f.y;
            }
        }

        // ---- refill stage s immediately (smem reads consumed by dataflow) ----
        {
            int pn = pair + STAGES * TW;
            if (pn < NP && elect1()) {
                int cnt = min(QPW, BQ - pn * QPW);
                u32 bytes = (u32)cnt * QBYTES;
                mbar_expect(mybar + 8u * s, bytes);
                bulk_g2s(myring_u + (u32)s * CHUNK_BYTES,
                         h + (size_t)pn * QPW * QFLOATS, bytes, mybar + 8u * s);
            }
        }

        // ---- reduce across lanes: 6 interleaved butterfly chains ----
        #pragma unroll
        for (int d = 16; d > 0; d >>= 1) {
            #pragma unroll
            for (int i = 0; i < QPW; i++)
                #pragma unroll
                for (int o = 0; o < 3; o++)
                    y[i][o] += __shfl_xor_sync(0xffffffffu, y[i][o], d);
        }

        // ---- store (+ bias dot, lane==o) ----
        #pragma unroll
        for (int i = 0; i < QPW; i++) {
            int q = qb + i;
            if (q < BQ && lane < 3) {
                u64 bd = 0ULL;
                #pragma unroll
                for (int kp = 0; kp < 4; kp++) bd = fma2(ap[i][kp], bpl[kp], bd);
                float2 f = unpack2(bd);
                float val = ((lane == 0) ? y[i][0] : (lane == 1) ? y[i][1] : y[i][2])
                            + f.x + f.y;
                out[3 * (size_t)q + lane] = val;
            }
        }
    }
}

// ---------------- launch ----------------
extern "C" void kernel_launch(void* const* d_in, const int* in_sizes, int n_in,
                              void* d_out, int out_size)
{
    (void)n_in; (void)out_size;
    const float* h    = (const float*)d_in[0];
    const float* cell = (const float*)d_in[1];
    const float* W    = (const float*)d_in[2];
    const float* B    = (const float*)d_in[3];
    float* out = (float*)d_out;

    const int BQ = in_sizes[1] / 2;

    int dev = 0;
    cudaGetDevice(&dev);
    int sm = 0;
    cudaDeviceGetAttribute(&sm, cudaDevAttrMultiProcessorCount, dev);
    if (sm <= 0) sm = 148;

    cudaFuncSetAttribute(gsr_kernel, cudaFuncAttributeMaxDynamicSharedMemorySize, SMEM_TOTAL);
    gsr_kernel<<<sm * CTAS_PER_SM, THREADS, SMEM_TOTAL>>>(h, cell, W, B, out, BQ);
}